// round 10
// baseline (speedup 1.0000x reference)
#include <cuda_runtime.h>
#include <cstdint>

// exp(X) for batched 32x32 symmetric fp32 via scaling-and-squaring, degree-8
// Paterson-Stockmeyer Taylor, relaxed radius theta=1.35 (7 matmuls typical).
// TWO matrices per warp: half-warp h owns matrix h, lane owns columns jj and
// jj+16. A-operand rows broadcast from smem (LDS.128, half-warps bank-disjoint
// via +16-word offset); B-operand columns in registers; 64-reg f32x2 acc.
// R10 = R9 minus both 64-reg epilogue arrays (inline pairwise epilogues,
// plain C++ smem accesses) plus k=0 peel (mul2 kills acc-init MOVs).

#define STRIDE 36               // floats per smem row (conflict-free, 16B aligned)
#define MATF   1152             // floats per matrix buffer (32*36)
#define MOFF   1168             // matrix-1 offset inside a buffer: +16-word bank shift
#define BUFF   2320             // floats per buffer (2 matrices)

typedef unsigned long long u64;

__device__ __forceinline__ u64 pk2(float lo, float hi) {
    u64 r; asm("mov.b64 %0, {%1, %2};" : "=l"(r) : "f"(lo), "f"(hi)); return r;
}
__device__ __forceinline__ void upk2(float& lo, float& hi, u64 v) {
    asm("mov.b64 {%0, %1}, %2;" : "=f"(lo), "=f"(hi) : "l"(v));
}
__device__ __forceinline__ void fma2(u64& d, u64 a, u64 b) {
    asm("fma.rn.f32x2 %0, %1, %2, %0;" : "+l"(d) : "l"(a), "l"(b));
}
__device__ __forceinline__ u64 mul2(u64 a, u64 b) {
    u64 d; asm("mul.rn.f32x2 %0, %1, %2;" : "=l"(d) : "l"(a), "l"(b)); return d;
}

// C(:,c0|c1) = A * b, A rows from smem (my matrix), b columns in registers.
__device__ __forceinline__ void mm2(uint32_t aBase, const float* bc0, const float* bc1,
                                    u64 acc0[16], u64 acc1[16]) {
    {   // k = 0 peeled: mul instead of fma (no zero-init MOVs)
        u64 bb0 = pk2(bc0[0], bc0[0]);
        u64 bb1 = pk2(bc1[0], bc1[0]);
#pragma unroll
        for (int q = 0; q < 8; ++q) {
            u64 a0, a1;
            asm volatile("ld.shared.v2.u64 {%0, %1}, [%2];"
                         : "=l"(a0), "=l"(a1) : "r"(aBase + (uint32_t)(q * 16)));
            acc0[2 * q]     = mul2(a0, bb0);
            acc0[2 * q + 1] = mul2(a1, bb0);
            acc1[2 * q]     = mul2(a0, bb1);
            acc1[2 * q + 1] = mul2(a1, bb1);
        }
    }
#pragma unroll
    for (int k = 1; k < 32; ++k) {
        u64 bb0 = pk2(bc0[k], bc0[k]);
        u64 bb1 = pk2(bc1[k], bc1[k]);
        uint32_t ra = aBase + (uint32_t)(k * STRIDE * 4);
#pragma unroll
        for (int q = 0; q < 8; ++q) {
            u64 a0, a1;
            asm volatile("ld.shared.v2.u64 {%0, %1}, [%2];"
                         : "=l"(a0), "=l"(a1) : "r"(ra + (uint32_t)(q * 16)));
            fma2(acc0[2 * q],     a0, bb0);
            fma2(acc0[2 * q + 1], a1, bb0);
            fma2(acc1[2 * q],     a0, bb1);
            fma2(acc1[2 * q + 1], a1, bb1);
        }
    }
}

__global__ void __launch_bounds__(32)
ExpEig_52553219834314_kernel(const float* __restrict__ in,
                             float* __restrict__ out, int B) {
    __shared__ __align__(16) float smem[3 * BUFF];

    const int lane = threadIdx.x;
    const int h = lane >> 4, jj = lane & 15;
    int mat = blockIdx.x * 2 + h;
    const bool alive = (mat < B);
    if (!alive) mat = B - 1;
    const int c0 = jj, c1 = jj + 16;

    float* myA = smem + h * MOFF;          // X -> Xs -> P (squaring chain)
    float* myB = myA + BUFF;               // X2s
    float* myD = myA + 2 * BUFF;           // B2 -> (M1+B1)
    const uint32_t aA = (uint32_t)__cvta_generic_to_shared(myA);
    const uint32_t aD = aA + (uint32_t)(2 * BUFF * 4);

    // Load X columns c0,c1 into regs; mirror full X into bufA (A-operand, stage 0).
    const float* src = in + (size_t)mat * 1024;
    float b0[32], b1[32];
#pragma unroll
    for (int i = 0; i < 32; ++i) { b0[i] = src[i * 32 + c0]; b1[i] = src[i * 32 + c1]; }
#pragma unroll
    for (int i = 0; i < 32; ++i) {
        myA[i * STRIDE + c0] = b0[i];
        myA[i * STRIDE + c1] = b1[i];
    }
    __syncwarp();

    u64 acc0[16], acc1[16];

    // ---- stage 0: X2 = X * X  (A = X smem, B = X regs)
    mm2(aA, b0, b1, acc0, acc1);

    // Spectral bound folded into the unpack (no persistent result array):
    // ||X||_2 <= sqrt(min(||X2||_1, ||X2||_F)).
    float rs, fb = 0.f;
    {
        float sa = 0.f, sb = 0.f;
#pragma unroll
        for (int p = 0; p < 16; ++p) {
            float t0, t1, u0, u1;
            upk2(t0, t1, acc0[p]); upk2(u0, u1, acc1[p]);
            sa += fabsf(t0) + fabsf(t1);
            sb += fabsf(u0) + fabsf(u1);
            fb += t0 * t0 + t1 * t1 + u0 * u0 + u1 * u1;
        }
        rs = fmaxf(sa, sb);
    }
#pragma unroll
    for (int off = 8; off > 0; off >>= 1) {   // reduce within half-warp (one matrix)
        rs = fmaxf(rs, __shfl_xor_sync(0xffffffffu, rs, off));
        fb += __shfl_xor_sync(0xffffffffu, fb, off);
    }
    float bnd = sqrtf(fminf(rs, sqrtf(fb)));
    bnd = fmaxf(bnd, __shfl_xor_sync(0xffffffffu, bnd, 16));  // uniform k across warp
    int e = 0; (void)frexpf(bnd * (1.f / 1.35f), &e);  // relaxed radius: ||Xs||<=1.35
    const int kk = e < 0 ? 0 : (e > 24 ? 24 : e);
    const int total = 4 + kk;
    const float s1 = exp2f(-(float)kk), s2 = s1 * s1;

    __syncwarp();   // stage-0 mm reads of A complete before Xs overwrite

    // Xs -> bufA (from b, which still holds X), X2s -> bufB and bcol (from acc).
#pragma unroll
    for (int p = 0; p < 16; ++p) {
        const int i0 = 2 * p, i1 = 2 * p + 1;
        myA[i0 * STRIDE + c0] = b0[i0] * s1;
        myA[i1 * STRIDE + c0] = b0[i1] * s1;
        myA[i0 * STRIDE + c1] = b1[i0] * s1;
        myA[i1 * STRIDE + c1] = b1[i1] * s1;
        float x00, x01, x10, x11;
        upk2(x00, x01, acc0[p]); upk2(x10, x11, acc1[p]);
        x00 *= s2; x01 *= s2; x10 *= s2; x11 *= s2;
        myB[i0 * STRIDE + c0] = x00;
        myB[i1 * STRIDE + c0] = x01;
        myB[i0 * STRIDE + c1] = x10;
        myB[i1 * STRIDE + c1] = x11;
        b0[i0] = x00; b0[i1] = x01;
        b1[i0] = x10; b1[i1] = x11;
    }
    __syncwarp();

    // ---- stage 1: Z = Xs * X2s  (A = Xs smem, B = X2s regs) -> Z stays in regs
    mm2(aA, b0, b1, acc0, acc1);
#pragma unroll
    for (int p = 0; p < 16; ++p) {           // unpack straight into bcol (Z)
        upk2(b0[2 * p], b0[2 * p + 1], acc0[p]);
        upk2(b1[2 * p], b1[2 * p + 1], acc1[p]);
    }
    __syncwarp();
    // Build B2 = I/720 + Xs/5040 + X2s/40320 -> bufD.
#pragma unroll
    for (int i = 0; i < 32; ++i) {
        float d0 = (i == c0) ? (1.f / 720.f) : 0.f;
        d0 += myA[i * STRIDE + c0] * (1.f / 5040.f);
        d0 += myB[i * STRIDE + c0] * (1.f / 40320.f);
        myD[i * STRIDE + c0] = d0;
        float d1 = (i == c1) ? (1.f / 720.f) : 0.f;
        d1 += myA[i * STRIDE + c1] * (1.f / 5040.f);
        d1 += myB[i * STRIDE + c1] * (1.f / 40320.f);
        myD[i * STRIDE + c1] = d1;
    }
    __syncwarp();

    // ---- stage 2: M1 = B2 * Z  (A = D smem, B = Z regs)
    mm2(aD, b0, b1, acc0, acc1);
    __syncwarp();   // mm reads of D complete before rewrite
    // D := M1 + B1, B1 = I/6 + Xs/24 + X2s/120  (inline pairwise, no arrays).
#pragma unroll
    for (int p = 0; p < 16; ++p) {
        const int i0 = 2 * p, i1 = 2 * p + 1;
        float m00, m01, m10, m11;
        upk2(m00, m01, acc0[p]); upk2(m10, m11, acc1[p]);
        myD[i0 * STRIDE + c0] = m00 + ((i0 == c0) ? (1.f / 6.f) : 0.f)
                              + myA[i0 * STRIDE + c0] * (1.f / 24.f)
                              + myB[i0 * STRIDE + c0] * (1.f / 120.f);
        myD[i1 * STRIDE + c0] = m01 + ((i1 == c0) ? (1.f / 6.f) : 0.f)
                              + myA[i1 * STRIDE + c0] * (1.f / 24.f)
                              + myB[i1 * STRIDE + c0] * (1.f / 120.f);
        myD[i0 * STRIDE + c1] = m10 + ((i0 == c1) ? (1.f / 6.f) : 0.f)
                              + myA[i0 * STRIDE + c1] * (1.f / 24.f)
                              + myB[i0 * STRIDE + c1] * (1.f / 120.f);
        myD[i1 * STRIDE + c1] = m11 + ((i1 == c1) ? (1.f / 6.f) : 0.f)
                              + myA[i1 * STRIDE + c1] * (1.f / 24.f)
                              + myB[i1 * STRIDE + c1] * (1.f / 120.f);
    }
    __syncwarp();

    // ---- stage 3: M2 = (M1+B1) * Z ; P = M2 + I + Xs + X2s/2
    mm2(aD, b0, b1, acc0, acc1);
#pragma unroll
    for (int p = 0; p < 16; ++p) {           // result into bcol, then add B0 terms
        upk2(b0[2 * p], b0[2 * p + 1], acc0[p]);
        upk2(b1[2 * p], b1[2 * p + 1], acc1[p]);
    }
    __syncwarp();
#pragma unroll
    for (int i = 0; i < 32; ++i) {
        b0[i] += ((i == c0) ? 1.f : 0.f) + myA[i * STRIDE + c0]
               + myB[i * STRIDE + c0] * 0.5f;
        b1[i] += ((i == c1) ? 1.f : 0.f) + myA[i * STRIDE + c1]
               + myB[i * STRIDE + c1] * 0.5f;
    }
    __syncwarp();   // all Xs/X2s reads done before P overwrites bufA
    if (total > 4) {
#pragma unroll
        for (int i = 0; i < 32; ++i) {
            myA[i * STRIDE + c0] = b0[i];
            myA[i * STRIDE + c1] = b1[i];
        }
    }
    __syncwarp();

    // ---- squarings: P = P * P  (A = P smem, B = P regs)
    for (int s = 4; s < total; ++s) {
        mm2(aA, b0, b1, acc0, acc1);
#pragma unroll
        for (int p = 0; p < 16; ++p) {
            upk2(b0[2 * p], b0[2 * p + 1], acc0[p]);
            upk2(b1[2 * p], b1[2 * p + 1], acc1[p]);
        }
        __syncwarp();
        if (s < total - 1) {                 // last squaring: result goes to gmem only
#pragma unroll
            for (int i = 0; i < 32; ++i) {
                myA[i * STRIDE + c0] = b0[i];
                myA[i * STRIDE + c1] = b1[i];
            }
        }
        __syncwarp();
    }

    if (alive) {
        float* dst = out + (size_t)mat * 1024;
#pragma unroll
        for (int i = 0; i < 32; ++i) {
            dst[i * 32 + c0] = b0[i];
            dst[i * 32 + c1] = b1[i];
        }
    }
}

extern "C" void kernel_launch(void* const* d_in, const int* in_sizes, int n_in,
                              void* d_out, int out_size) {
    (void)n_in; (void)out_size;
    const float* x = (const float*)d_in[0];
    float* out = (float*)d_out;
    const int B = in_sizes[0] / 1024;
    const int ctas = (B + 1) / 2;
    ExpEig_52553219834314_kernel<<<ctas, 32>>>(x, out, B);
}